// round 5
// baseline (speedup 1.0000x reference)
#include <cuda_runtime.h>
#include <math.h>

#define NUM_E 640000
#define NUM_N 20000
#define NUM_H 8

// Scratch (allocation-free rule: __device__ globals)
__device__ __align__(16) float g_tscore[NUM_N * NUM_H];  // x_e[t] . w[h,16:]
__device__ __align__(16) float g_segsum[NUM_N * NUM_H];  // sum(exp) then recip

// ---------------------------------------------------------------------------
// K1: per-node target scores + zero segsum. One warp per 4 nodes (MLP=4).
#define NODES_PER_WARP 4
__global__ void k_tscore(const float* __restrict__ x_e,
                         const float* __restrict__ weight) {
    int gtid = blockIdx.x * blockDim.x + threadIdx.x;
    int warp = gtid >> 5;
    int lane = gtid & 31;
    int n0 = warp * NODES_PER_WARP;
    if (n0 >= NUM_N) return;

    const float4* x4p = reinterpret_cast<const float4*>(x_e);
    float4 x[NODES_PER_WARP];
#pragma unroll
    for (int i = 0; i < NODES_PER_WARP; i++)
        x[i] = x4p[(size_t)(n0 + i) * 32 + lane];

    int h = lane >> 2, q = lane & 3;
    float4 w4 = reinterpret_cast<const float4*>(weight)[h * 8 + 4 + q];

#pragma unroll
    for (int i = 0; i < NODES_PER_WARP; i++) {
        float p = x[i].x * w4.x + x[i].y * w4.y + x[i].z * w4.z + x[i].w * w4.w;
        p += __shfl_xor_sync(0xffffffffu, p, 1);
        p += __shfl_xor_sync(0xffffffffu, p, 2);
        if (q == 0) {
            g_tscore[(n0 + i) * NUM_H + h] = p;
            g_segsum[(n0 + i) * NUM_H + h] = 0.0f;
        }
    }
}

// ---------------------------------------------------------------------------
// K2: fused copy + dot + LeakyReLU + exp + alpha numerator + segsum atomic.
// One warp per 8 edges (8 front-batched float4 loads per thread).
#define EDGES_PER_WARP 8
__global__ void k_edge(const float* __restrict__ message,
                       const int* __restrict__ target,
                       const float* __restrict__ weight,
                       float* __restrict__ out_msg,
                       float* __restrict__ out_alpha) {
    int gtid = blockIdx.x * blockDim.x + threadIdx.x;
    int warp = gtid >> 5;
    int lane = gtid & 31;
    int e0 = warp * EDGES_PER_WARP;
    if (e0 >= NUM_E) return;

    const float4* msg4 = reinterpret_cast<const float4*>(message);
    float4*       out4 = reinterpret_cast<float4*>(out_msg);

    float4 m[EDGES_PER_WARP];
#pragma unroll
    for (int i = 0; i < EDGES_PER_WARP; i++)
        m[i] = __ldcs(&msg4[(size_t)(e0 + i) * 32 + lane]);   // streaming read
#pragma unroll
    for (int i = 0; i < EDGES_PER_WARP; i++)
        __stcs(&out4[(size_t)(e0 + i) * 32 + lane], m[i]);    // streaming write

    int h = lane >> 2, q = lane & 3;
    float4 w4 = reinterpret_cast<const float4*>(weight)[h * 8 + q];  // msg half

#pragma unroll
    for (int i = 0; i < EDGES_PER_WARP; i++) {
        float p = m[i].x * w4.x + m[i].y * w4.y + m[i].z * w4.z + m[i].w * w4.w;
        p += __shfl_xor_sync(0xffffffffu, p, 1);
        p += __shfl_xor_sync(0xffffffffu, p, 2);
        if (q == 0) {
            int e = e0 + i;
            int t = target[e];
            float s = p + g_tscore[t * NUM_H + h];
            s = (s >= 0.0f) ? s : 0.01f * s;          // LeakyReLU
            float ex = __expf(s);                     // no max-shift (safe)
            out_alpha[e * NUM_H + h] = ex;
            atomicAdd(&g_segsum[t * NUM_H + h], ex);
        }
    }
}

// ---------------------------------------------------------------------------
// K2.5: reciprocal of segment sums (turns k_norm divisions into multiplies)
__global__ void k_recip() {
    int i = blockIdx.x * blockDim.x + threadIdx.x;
    if (i < NUM_N * NUM_H)
        g_segsum[i] = 1.0f / (g_segsum[i] + 1e-16f);
}

// ---------------------------------------------------------------------------
// K3: normalize alpha. 4 edges per thread, grid-stride spacing (perfect
// per-instruction coalescing, MLP batched: targets -> gathers -> alphas).
#define NORM_EPT 4
__global__ void k_norm(const int* __restrict__ target,
                       float* __restrict__ out_alpha) {
    const int S = NUM_E / NORM_EPT;  // 160000
    int tid = blockIdx.x * blockDim.x + threadIdx.x;
    if (tid >= S) return;

    int e[NORM_EPT];
#pragma unroll
    for (int i = 0; i < NORM_EPT; i++) e[i] = tid + i * S;

    int t[NORM_EPT];
#pragma unroll
    for (int i = 0; i < NORM_EPT; i++) t[i] = target[e[i]];

    const float4* rs4 = reinterpret_cast<const float4*>(g_segsum);
    float4 r0[NORM_EPT], r1[NORM_EPT];
#pragma unroll
    for (int i = 0; i < NORM_EPT; i++) {
        r0[i] = rs4[t[i] * 2 + 0];
        r1[i] = rs4[t[i] * 2 + 1];
    }

    float4* a4 = reinterpret_cast<float4*>(out_alpha);
    float4 a0[NORM_EPT], a1[NORM_EPT];
#pragma unroll
    for (int i = 0; i < NORM_EPT; i++) {
        a0[i] = a4[e[i] * 2 + 0];
        a1[i] = a4[e[i] * 2 + 1];
    }

#pragma unroll
    for (int i = 0; i < NORM_EPT; i++) {
        a0[i].x *= r0[i].x; a0[i].y *= r0[i].y;
        a0[i].z *= r0[i].z; a0[i].w *= r0[i].w;
        a1[i].x *= r1[i].x; a1[i].y *= r1[i].y;
        a1[i].z *= r1[i].z; a1[i].w *= r1[i].w;
        a4[e[i] * 2 + 0] = a0[i];
        a4[e[i] * 2 + 1] = a1[i];
    }
}

// ---------------------------------------------------------------------------
extern "C" void kernel_launch(void* const* d_in, const int* in_sizes, int n_in,
                              void* d_out, int out_size) {
    const int*   edge_index = (const int*)d_in[0];    // (2, E) int32
    const float* message    = (const float*)d_in[1];  // (E, 128)
    const float* x_e        = (const float*)d_in[2];  // (N, 128)
    const float* weight     = (const float*)d_in[3];  // (8, 32)

    const int* target = edge_index + NUM_E;  // row 1

    float* out_msg   = (float*)d_out;                  // E*128 floats
    float* out_alpha = out_msg + (size_t)NUM_E * 128;  // E*8 floats

    const int TPB = 256;

    {   // k_tscore: one warp per 4 nodes
        int warps = (NUM_N + NODES_PER_WARP - 1) / NODES_PER_WARP;  // 5000
        k_tscore<<<(warps * 32 + TPB - 1) / TPB, TPB>>>(x_e, weight);
    }
    {   // k_edge: one warp per 8 edges
        int warps = NUM_E / EDGES_PER_WARP;              // 80000
        k_edge<<<(warps * 32 + TPB - 1) / TPB, TPB>>>(message, target, weight,
                                                      out_msg, out_alpha);
    }
    k_recip<<<(NUM_N * NUM_H + TPB - 1) / TPB, TPB>>>();
    k_norm<<<(NUM_E / NORM_EPT + TPB - 1) / TPB, TPB>>>(target, out_alpha);
}

// round 6
// speedup vs baseline: 1.0345x; 1.0345x over previous
#include <cuda_runtime.h>
#include <math.h>

#define NUM_E 640000
#define NUM_N 20000
#define NUM_H 8

// Scratch (allocation-free rule: __device__ globals)
__device__ __align__(16) float g_tscore[NUM_N * NUM_H];  // x_e[t] . w[h,16:]
__device__ __align__(16) float g_segsum[NUM_N * NUM_H];  // sum(exp) then recip

// ---------------------------------------------------------------------------
// K1: per-node target scores + zero segsum. One warp per 4 nodes.
#define NODES_PER_WARP 4
__global__ void k_tscore(const float* __restrict__ x_e,
                         const float* __restrict__ weight) {
    int gtid = blockIdx.x * blockDim.x + threadIdx.x;
    int warp = gtid >> 5;
    int lane = gtid & 31;
    int n0 = warp * NODES_PER_WARP;
    if (n0 >= NUM_N) return;

    const float4* x4p = reinterpret_cast<const float4*>(x_e);
    float4 x[NODES_PER_WARP];
#pragma unroll
    for (int i = 0; i < NODES_PER_WARP; i++)
        x[i] = x4p[(size_t)(n0 + i) * 32 + lane];

    int h = lane >> 2, q = lane & 3;
    float4 w4 = reinterpret_cast<const float4*>(weight)[h * 8 + 4 + q];

#pragma unroll
    for (int i = 0; i < NODES_PER_WARP; i++) {
        float p = x[i].x * w4.x + x[i].y * w4.y + x[i].z * w4.z + x[i].w * w4.w;
        p += __shfl_xor_sync(0xffffffffu, p, 1);
        p += __shfl_xor_sync(0xffffffffu, p, 2);
        if (q == 0) {
            g_tscore[(n0 + i) * NUM_H + h] = p;
            g_segsum[(n0 + i) * NUM_H + h] = 0.0f;
        }
    }
}

// ---------------------------------------------------------------------------
// K2: fused copy + dot + LeakyReLU + exp + alpha numerator + segsum atomic.
// One warp per 4 edges (R4-measured best config).
#define EDGES_PER_WARP 4
__global__ void k_edge(const float* __restrict__ message,
                       const int* __restrict__ target,
                       const float* __restrict__ weight,
                       float* __restrict__ out_msg,
                       float* __restrict__ out_alpha) {
    int gtid = blockIdx.x * blockDim.x + threadIdx.x;
    int warp = gtid >> 5;
    int lane = gtid & 31;
    int e0 = warp * EDGES_PER_WARP;
    if (e0 >= NUM_E) return;

    const float4* msg4 = reinterpret_cast<const float4*>(message);
    float4*       out4 = reinterpret_cast<float4*>(out_msg);

    float4 m[EDGES_PER_WARP];
#pragma unroll
    for (int i = 0; i < EDGES_PER_WARP; i++)
        m[i] = __ldcs(&msg4[(size_t)(e0 + i) * 32 + lane]);   // streaming read
#pragma unroll
    for (int i = 0; i < EDGES_PER_WARP; i++)
        __stcs(&out4[(size_t)(e0 + i) * 32 + lane], m[i]);    // streaming write

    int h = lane >> 2, q = lane & 3;
    float4 w4 = reinterpret_cast<const float4*>(weight)[h * 8 + q];  // msg half

#pragma unroll
    for (int i = 0; i < EDGES_PER_WARP; i++) {
        float p = m[i].x * w4.x + m[i].y * w4.y + m[i].z * w4.z + m[i].w * w4.w;
        p += __shfl_xor_sync(0xffffffffu, p, 1);
        p += __shfl_xor_sync(0xffffffffu, p, 2);
        if (q == 0) {
            int e = e0 + i;
            int t = target[e];
            float s = p + g_tscore[t * NUM_H + h];
            s = (s >= 0.0f) ? s : 0.01f * s;          // LeakyReLU
            float ex = __expf(s);                     // no max-shift (safe)
            out_alpha[e * NUM_H + h] = ex;
            atomicAdd(&g_segsum[t * NUM_H + h], ex);
        }
    }
}

// ---------------------------------------------------------------------------
// K2.5: reciprocal of segment sums (turns k_norm divisions into multiplies)
__global__ void k_recip() {
    int i = blockIdx.x * blockDim.x + threadIdx.x;
    if (i < NUM_N * NUM_H)
        g_segsum[i] = 1.0f / (g_segsum[i] + 1e-16f);
}

// ---------------------------------------------------------------------------
// K3: normalize alpha. 2 edges per thread (320k threads), with independent
// loads (targets + alphas) issued BEFORE the target-dependent gathers.
#define NORM_EPT 2
__global__ void k_norm(const int* __restrict__ target,
                       float* __restrict__ out_alpha) {
    const int S = NUM_E / NORM_EPT;  // 320000
    int tid = blockIdx.x * blockDim.x + threadIdx.x;
    if (tid >= S) return;

    int e0 = tid;
    int e1 = tid + S;

    // Independent loads first: targets (L2-hot from k_edge) + alphas.
    int t0 = target[e0];
    int t1 = target[e1];

    float4* a4 = reinterpret_cast<float4*>(out_alpha);
    float4 a00 = a4[e0 * 2 + 0];
    float4 a01 = a4[e0 * 2 + 1];
    float4 a10 = a4[e1 * 2 + 0];
    float4 a11 = a4[e1 * 2 + 1];

    // Dependent gathers (small hot table).
    const float4* rs4 = reinterpret_cast<const float4*>(g_segsum);
    float4 r00 = rs4[t0 * 2 + 0];
    float4 r01 = rs4[t0 * 2 + 1];
    float4 r10 = rs4[t1 * 2 + 0];
    float4 r11 = rs4[t1 * 2 + 1];

    a00.x *= r00.x; a00.y *= r00.y; a00.z *= r00.z; a00.w *= r00.w;
    a01.x *= r01.x; a01.y *= r01.y; a01.z *= r01.z; a01.w *= r01.w;
    a10.x *= r10.x; a10.y *= r10.y; a10.z *= r10.z; a10.w *= r10.w;
    a11.x *= r11.x; a11.y *= r11.y; a11.z *= r11.z; a11.w *= r11.w;

    a4[e0 * 2 + 0] = a00;
    a4[e0 * 2 + 1] = a01;
    a4[e1 * 2 + 0] = a10;
    a4[e1 * 2 + 1] = a11;
}

// ---------------------------------------------------------------------------
extern "C" void kernel_launch(void* const* d_in, const int* in_sizes, int n_in,
                              void* d_out, int out_size) {
    const int*   edge_index = (const int*)d_in[0];    // (2, E) int32
    const float* message    = (const float*)d_in[1];  // (E, 128)
    const float* x_e        = (const float*)d_in[2];  // (N, 128)
    const float* weight     = (const float*)d_in[3];  // (8, 32)

    const int* target = edge_index + NUM_E;  // row 1

    float* out_msg   = (float*)d_out;                  // E*128 floats
    float* out_alpha = out_msg + (size_t)NUM_E * 128;  // E*8 floats

    const int TPB = 256;

    {   // k_tscore: one warp per 4 nodes
        int warps = (NUM_N + NODES_PER_WARP - 1) / NODES_PER_WARP;  // 5000
        k_tscore<<<(warps * 32 + TPB - 1) / TPB, TPB>>>(x_e, weight);
    }
    {   // k_edge: one warp per 4 edges
        int warps = NUM_E / EDGES_PER_WARP;              // 160000
        k_edge<<<(warps * 32 + TPB - 1) / TPB, TPB>>>(message, target, weight,
                                                      out_msg, out_alpha);
    }
    k_recip<<<(NUM_N * NUM_H + TPB - 1) / TPB, TPB>>>();
    k_norm<<<(NUM_E / NORM_EPT + TPB - 1) / TPB, TPB>>>(target, out_alpha);
}